// round 14
// baseline (speedup 1.0000x reference)
#include <cuda_runtime.h>
#include <cuda_fp16.h>

#define NPTS  (1u << 18)
#define TMASK 0x3FFFFFu
#define PI2C  2654435761u
#define FSCALE 16384.0f              // 2^14: lift features into fp16 normal range
#define INV_FSCALE 6.103515625e-05f  // 2^-14, exact power of two
#define PTS_PER_WARP 32

// NL[l] = floor(16 * 1.26^l) per reference fp32 math
__device__ __constant__ float c_NL[16] = {
    16.f, 20.f, 25.f, 32.f, 40.f, 50.f, 64.f, 80.f,
    101.f, 128.f, 161.f, 203.f, 256.f, 322.f, 406.f, 512.f
};
__device__ __constant__ int c_NLi[16] = {
    16, 20, 25, 32, 40, 50, 64, 80, 101, 128, 161, 203, 256, 322, 406, 512
};
// ceil(NL/2) for the 2x2-window blockify tiling
__device__ __constant__ int c_NL2[16] = {
    8, 10, 13, 16, 20, 25, 32, 40, 51, 64, 81, 102, 128, 161, 203, 256
};
// Cell-grid width per level: W = NL + 3
__device__ __constant__ int c_W[16] = {
    19, 23, 28, 35, 43, 53, 67, 83, 104, 131, 164, 206, 259, 325, 409, 515
};
// Prefix sums of W^2 (pass-1 dense cell grid)
__device__ __constant__ int c_base[16] = {
    0, 361, 890, 1674, 2899, 4748, 7557, 12046,
    18935, 29751, 46912, 73808, 116244, 183325, 288950, 456231
};
#define DENSE1_TOTAL 721456
// Prefix sums of NL^2 (pass-2 window-block grid)
__device__ __constant__ int c_bbase[16] = {
    0, 256, 656, 1281, 2305, 3905, 6405, 10501,
    16901, 27102, 43486, 69407, 110616, 176152, 279836, 444672
};
#define NBLK_TOTAL 706816
// Block-row stride in bytes for main kernel: NLi * 64
__device__ __constant__ int c_strideB[16] = {
    1024, 1280, 1600, 2048, 2560, 3200, 4096, 5120,
    6464, 8192, 10304, 12992, 16384, 20608, 25984, 32768
};

// Pass-1 scratch: dense per-level cell grids, fp16 feature pairs (2.9 MB)
__device__ __half2 g_dense1[DENSE1_TOTAL];

// Pass-2 scratch: one 64B-aligned block per possible 4x4 window (45.2 MB).
// c[j*4+i] = features of cell (bx+i, by+j).
struct __align__(64) Blk { __half2 c[16]; };
__device__ Blk g_blocks[NBLK_TOTAL];

// ---------------------------------------------------------------------------
// Pass 1: hash once per reachable cell. 2 cells per thread -> 4 gathers in
// flight (densify was latency-exposed: issue 18%, DRAM 25%).
// ---------------------------------------------------------------------------
__global__ void __launch_bounds__(256)
densify_kernel(const float* __restrict__ tab) {
    int l = blockIdx.y;
    int W = c_W[l];
    int tot = W * W;
    int idx0 = (blockIdx.x * 256 + threadIdx.x) * 2;
    if (idx0 >= tot) return;
    int cy0 = idx0 / W;
    int cx0 = idx0 - cy0 * W;
    unsigned h0 = (((unsigned)cx0) ^ ((unsigned)cy0 * PI2C)) & TMASK;

    int idx1 = idx0 + 1;
    bool has1 = idx1 < tot;
    int cx1 = cx0 + 1, cy1 = cy0;
    if (cx1 == W) { cx1 = 0; cy1 = cy0 + 1; }
    unsigned h1 = (((unsigned)cx1) ^ ((unsigned)cy1 * PI2C)) & TMASK;

    const float* r0 = tab + h0 * 32u;
    const float* r1 = tab + (has1 ? h1 * 32u : h0 * 32u);
    float a0 = __ldg(r0 + l), b0 = __ldg(r0 + l + 16);
    float a1 = __ldg(r1 + l), b1 = __ldg(r1 + l + 16);

    g_dense1[c_base[l] + idx0] = __floats2half2_rn(a0 * FSCALE, b0 * FSCALE);
    if (has1)
        g_dense1[c_base[l] + idx1] = __floats2half2_rn(a1 * FSCALE, b1 * FSCALE);
}

// ---------------------------------------------------------------------------
// Pass 2: expand cell grid into per-window 64B blocks. Each thread builds a
// 2x2 quad of windows from one clamped 5x5 cell patch (25 reads / 4 windows
// instead of 64). Clamped reads only feed windows that are guarded out.
// ---------------------------------------------------------------------------
__global__ void __launch_bounds__(256)
blockify_kernel() {
    int l = blockIdx.y;
    int NLi = c_NLi[l];
    int NL2 = c_NL2[l];
    int nq = NL2 * NL2;
    int idx = blockIdx.x * 256 + threadIdx.x;
    if (idx >= nq) return;
    int qy = idx / NL2;
    int qx = idx - qy * NL2;
    int bx0 = qx * 2, by0 = qy * 2;
    int W = c_W[l];
    const __half2* src = g_dense1 + c_base[l];

    // Clamped 5x5 patch
    __half2 r[5][5];
    int cxs[5], cys[5];
#pragma unroll
    for (int k = 0; k < 5; ++k) {
        cxs[k] = min(bx0 + k, W - 1);
        cys[k] = min(by0 + k, W - 1) * W;
    }
#pragma unroll
    for (int j = 0; j < 5; ++j)
#pragma unroll
        for (int i = 0; i < 5; ++i)
            r[j][i] = src[cys[j] + cxs[i]];

    Blk* bb = g_blocks + c_bbase[l];
#pragma unroll
    for (int dy = 0; dy < 2; ++dy) {
#pragma unroll
        for (int dx = 0; dx < 2; ++dx) {
            int wx = bx0 + dx, wy = by0 + dy;
            if (wx < NLi && wy < NLi) {
                Blk* dst = bb + wy * NLi + wx;
#pragma unroll
                for (int j = 0; j < 4; ++j) {
                    __half2 row[4];
#pragma unroll
                    for (int i = 0; i < 4; ++i) row[i] = r[dy + j][dx + i];
                    reinterpret_cast<float4*>(dst->c)[j] =
                        *reinterpret_cast<float4*>(row);
                }
            }
        }
    }
}

// Catmull-Rom weight polynomial coefficients for tap k: w_k(t)=At^3+Bt^2+Ct+D
__device__ __forceinline__ void cub_coef(int k, float& A, float& B, float& C, float& D) {
    if (k == 0)      { A = -0.5f; B =  1.0f; C = -0.5f; D = 0.f; }
    else if (k == 1) { A =  1.5f; B = -2.5f; C =  0.0f; D = 1.f; }
    else if (k == 2) { A = -1.5f; B =  2.0f; C =  0.5f; D = 0.f; }
    else             { A =  0.5f; B = -0.5f; C =  0.0f; D = 0.f; }
}

// ---------------------------------------------------------------------------
// Main kernel: 4 lanes per (point, level) window; warp role covers 8 levels.
// Each lane: one LDG.128 window row, fp32 row dot, 3-shuffle quad reduction,
// lanes 0 and 2 of each quad store one feature scalar (64B contiguous/warp).
// ---------------------------------------------------------------------------
__global__ void __launch_bounds__(256)
enc_cubic_kernel(const float* __restrict__ x,
                 float* __restrict__ out) {
    unsigned gw = (blockIdx.x * 256u + threadIdx.x) >> 5;   // global warp id
    int lane = threadIdx.x & 31;
    int role = gw & 1;
    unsigned pbase = (gw >> 1) * PTS_PER_WARP;

    int l = role * 8 + (lane >> 2);       // this lane's level
    int j = lane & 3;                     // this lane's window row

    // Lane-constant state
    float NL = c_NL[l];
    int strideB = c_strideB[l];
    const char* bp = reinterpret_cast<const char*>(g_blocks)
                   + (size_t)c_bbase[l] * 64u + (size_t)(j * 16);
    float Ay, By, Cy, Dy;
    cub_coef(j, Ay, By, Cy, Dy);
    Ay *= INV_FSCALE; By *= INV_FSCALE; Cy *= INV_FSCALE; Dy *= INV_FSCALE;

    const float2* xp = reinterpret_cast<const float2*>(x);
    // Lanes 0 and 2 of each quad store feature 0 / feature 1 respectively
    bool storer = (lane & 1) == 0;
    int ocol = l * 2 + ((lane >> 1) & 1);

#pragma unroll 8
    for (int it = 0; it < PTS_PER_WARP; ++it) {
        unsigned n = pbase + it;
        float2 p = __ldg(&xp[n]);         // uniform across warp
        float xs = p.x * NL;
        float ys = p.y * NL;
        int ixi = (int)xs;
        int iyi = (int)ys;
        float lx = xs - (float)ixi;
        float ly = ys - (float)iyi;

        const float4* rowp = reinterpret_cast<const float4*>(
            bp + (size_t)iyi * (size_t)strideB + (size_t)(ixi * 64));
        float4 r = __ldg(rowp);

        float x2 = lx * lx;
        float wx0 = lx * fmaf(lx, fmaf(lx, -0.5f, 1.0f), -0.5f);
        float wx1 = fmaf(x2, fmaf(lx, 1.5f, -2.5f), 1.0f);
        float wx2 = lx * fmaf(lx, fmaf(lx, -1.5f, 2.0f), 0.5f);
        float wx3 = x2 * fmaf(lx, 0.5f, -0.5f);
        float wy = fmaf(fmaf(fmaf(Ay, ly, By), ly, Cy), ly, Dy);

        const __half2* h = reinterpret_cast<const __half2*>(&r);
        float2 c0 = __half22float2(h[0]);
        float2 c1 = __half22float2(h[1]);
        float2 c2 = __half22float2(h[2]);
        float2 c3 = __half22float2(h[3]);
        float d0 = fmaf(wx3, c3.x, fmaf(wx2, c2.x, fmaf(wx1, c1.x, wx0 * c0.x)));
        float d1 = fmaf(wx3, c3.y, fmaf(wx2, c2.y, fmaf(wx1, c1.y, wx0 * c0.y)));
        float v0 = d0 * wy;
        float v1 = d1 * wy;

        // Feature-split quad reduction: 3 shuffles.
        float p0 = __shfl_xor_sync(0xffffffffu, v0, 2);
        float p1 = __shfl_xor_sync(0xffffffffu, v1, 2);
        float s = (lane & 2) ? (v1 + p1) : (v0 + p0);
        s += __shfl_xor_sync(0xffffffffu, s, 1);
        // lane0 of quad: feature0 sum; lane2: feature1 sum

        if (storer)
            out[n * 32u + ocol] = s;
    }
}

extern "C" void kernel_launch(void* const* d_in, const int* in_sizes, int n_in,
                              void* d_out, int out_size) {
    const float* x   = (const float*)d_in[0];   // (262144, 2) float32
    const float* tab = (const float*)d_in[1];   // (2^22, 2, 16) float32
    float* out = (float*)d_out;                 // (262144, 32) float32

    // Pass 1: dense cell grids, 2 cells/thread (max ceil(W^2/2) = 132613)
    dim3 g1((132613 + 255) / 256, 16);
    densify_kernel<<<g1, 256>>>(tab);

    // Pass 2: window blocks, 2x2 windows/thread (max NL2^2 = 65536)
    dim3 g2(65536 / 256, 16);
    blockify_kernel<<<g2, 256>>>();

    // Main: 2 warp-roles per point-stream
    unsigned total_warps = (NPTS / PTS_PER_WARP) * 2;       // 16384 warps
    enc_cubic_kernel<<<total_warps * 32 / 256, 256>>>(x, out);
}

// round 15
// speedup vs baseline: 1.3666x; 1.3666x over previous
#include <cuda_runtime.h>
#include <cuda_fp16.h>

#define NPTS  (1u << 18)
#define TMASK 0x3FFFFFu
#define PI2C  2654435761u
#define FSCALE 16384.0f              // 2^14: lift features into fp16 normal range
#define INV_FSCALE 6.103515625e-05f  // 2^-14, exact power of two
#define PTS_PER_WARP 32

// NL[l] = floor(16 * 1.26^l) per reference fp32 math
__device__ __constant__ float c_NL[16] = {
    16.f, 20.f, 25.f, 32.f, 40.f, 50.f, 64.f, 80.f,
    101.f, 128.f, 161.f, 203.f, 256.f, 322.f, 406.f, 512.f
};
__device__ __constant__ int c_NLi[16] = {
    16, 20, 25, 32, 40, 50, 64, 80, 101, 128, 161, 203, 256, 322, 406, 512
};
// Cell-grid width per level: W = NL + 3
__device__ __constant__ int c_W[16] = {
    19, 23, 28, 35, 43, 53, 67, 83, 104, 131, 164, 206, 259, 325, 409, 515
};
// Prefix sums of W^2 (pass-1 dense cell grid)
__device__ __constant__ int c_base[16] = {
    0, 361, 890, 1674, 2899, 4748, 7557, 12046,
    18935, 29751, 46912, 73808, 116244, 183325, 288950, 456231
};
#define DENSE1_TOTAL 721456
// Prefix sums of NL^2 (pass-2 window-block grid)
__device__ __constant__ int c_bbase[16] = {
    0, 256, 656, 1281, 2305, 3905, 6405, 10501,
    16901, 27102, 43486, 69407, 110616, 176152, 279836, 444672
};
#define NBLK_TOTAL 706816
// Block-row stride in bytes for main kernel: NLi * 64
__device__ __constant__ int c_strideB[16] = {
    1024, 1280, 1600, 2048, 2560, 3200, 4096, 5120,
    6464, 8192, 10304, 12992, 16384, 20608, 25984, 32768
};

// Pass-1 scratch: dense per-level cell grids, fp16 feature pairs (2.9 MB)
__device__ __half2 g_dense1[DENSE1_TOTAL];

// Pass-2 scratch: one 64B-aligned block per possible 4x4 window (45.2 MB).
// c[j*4+i] = features of cell (bx+i, by+j).
struct __align__(64) Blk { __half2 c[16]; };
__device__ Blk g_blocks[NBLK_TOTAL];

// ---------------------------------------------------------------------------
// Pass 1 (R13 version): hash once per reachable cell, one cell per thread.
// ---------------------------------------------------------------------------
__global__ void __launch_bounds__(256)
densify_kernel(const float* __restrict__ tab) {
    int l = blockIdx.y;
    int W = c_W[l];
    int tot = W * W;
    int idx = blockIdx.x * 256 + threadIdx.x;
    if (idx >= tot) return;
    int cy = idx / W;
    int cx = idx - cy * W;
    unsigned h = (((unsigned)cx) ^ ((unsigned)cy * PI2C)) & TMASK;
    const float* r = tab + h * 32u;
    g_dense1[c_base[l] + idx] =
        __floats2half2_rn(__ldg(r + l) * FSCALE, __ldg(r + l + 16) * FSCALE);
}

// ---------------------------------------------------------------------------
// Pass 2 (R13 version): one window per thread; coalesced-ish float4 writes.
// ---------------------------------------------------------------------------
__global__ void __launch_bounds__(256)
blockify_kernel() {
    int l = blockIdx.y;
    int NLi = c_NLi[l];
    int nblk = NLi * NLi;
    int idx = blockIdx.x * 256 + threadIdx.x;
    if (idx >= nblk) return;
    int by = idx / NLi;
    int bx = idx - by * NLi;
    int W = c_W[l];
    const __half2* src = g_dense1 + c_base[l] + by * W + bx;
    Blk* dst = g_blocks + c_bbase[l] + idx;
#pragma unroll
    for (int j = 0; j < 4; ++j) {
        float4 row;
        __half2* rc = reinterpret_cast<__half2*>(&row);
#pragma unroll
        for (int i = 0; i < 4; ++i) rc[i] = src[j * W + i];
        reinterpret_cast<float4*>(dst->c)[j] = row;
    }
}

// Catmull-Rom weight polynomial coefficients for tap k: w_k(t)=At^3+Bt^2+Ct+D
__device__ __forceinline__ void cub_coef(int k, float& A, float& B, float& C, float& D) {
    if (k == 0)      { A = -0.5f; B =  1.0f; C = -0.5f; D = 0.f; }
    else if (k == 1) { A =  1.5f; B = -2.5f; C =  0.0f; D = 1.f; }
    else if (k == 2) { A = -1.5f; B =  2.0f; C =  0.5f; D = 0.f; }
    else             { A =  0.5f; B = -0.5f; C =  0.0f; D = 0.f; }
}

// Per-point helper: full window-row processing for one point given its
// loaded row r and local coords (lx, ly). Returns this lane's weighted value
// pair (v0 = feat0, v1 = feat1).
__device__ __forceinline__ void lane_eval(float4 r, float lx, float ly,
                                          float Ay, float By, float Cy, float Dy,
                                          float& v0, float& v1) {
    float x2 = lx * lx;
    float wx0 = lx * fmaf(lx, fmaf(lx, -0.5f, 1.0f), -0.5f);
    float wx1 = fmaf(x2, fmaf(lx, 1.5f, -2.5f), 1.0f);
    float wx2 = lx * fmaf(lx, fmaf(lx, -1.5f, 2.0f), 0.5f);
    float wx3 = x2 * fmaf(lx, 0.5f, -0.5f);
    float wy = fmaf(fmaf(fmaf(Ay, ly, By), ly, Cy), ly, Dy);

    const __half2* h = reinterpret_cast<const __half2*>(&r);
    float2 c0 = __half22float2(h[0]);
    float2 c1 = __half22float2(h[1]);
    float2 c2 = __half22float2(h[2]);
    float2 c3 = __half22float2(h[3]);
    float d0 = fmaf(wx3, c3.x, fmaf(wx2, c2.x, fmaf(wx1, c1.x, wx0 * c0.x)));
    float d1 = fmaf(wx3, c3.y, fmaf(wx2, c2.y, fmaf(wx1, c1.y, wx0 * c0.y)));
    v0 = d0 * wy;
    v1 = d1 * wy;
}

// ---------------------------------------------------------------------------
// Main kernel: 4 lanes per (point, level) window; warp role covers 8 levels.
// TWO points per loop iteration with interleaved chains: both window LDGs
// issue back-to-back (16 lines in flight/warp) and point B's load latency
// hides behind point A's dot + shuffle chain.
// ---------------------------------------------------------------------------
__global__ void __launch_bounds__(256)
enc_cubic_kernel(const float* __restrict__ x,
                 float* __restrict__ out) {
    unsigned gw = (blockIdx.x * 256u + threadIdx.x) >> 5;   // global warp id
    int lane = threadIdx.x & 31;
    int role = gw & 1;
    unsigned pbase = (gw >> 1) * PTS_PER_WARP;

    int l = role * 8 + (lane >> 2);       // this lane's level
    int j = lane & 3;                     // this lane's window row

    // Lane-constant state
    float NL = c_NL[l];
    int strideB = c_strideB[l];
    const char* bp = reinterpret_cast<const char*>(g_blocks)
                   + (size_t)c_bbase[l] * 64u + (size_t)(j * 16);
    float Ay, By, Cy, Dy;
    cub_coef(j, Ay, By, Cy, Dy);
    Ay *= INV_FSCALE; By *= INV_FSCALE; Cy *= INV_FSCALE; Dy *= INV_FSCALE;

    const float2* xp = reinterpret_cast<const float2*>(x);
    // Lanes 0 and 2 of each quad store feature 0 / feature 1 respectively
    bool storer = (lane & 1) == 0;
    int ocol = l * 2 + ((lane >> 1) & 1);

#pragma unroll 2
    for (int it = 0; it < PTS_PER_WARP; it += 2) {
        unsigned na = pbase + it;
        unsigned nb = na + 1;

        // --- issue both point loads ---
        float2 pa = __ldg(&xp[na]);
        float2 pb = __ldg(&xp[nb]);

        // --- addresses for both, then both window loads back-to-back ---
        float xsa = pa.x * NL, ysa = pa.y * NL;
        float xsb = pb.x * NL, ysb = pb.y * NL;
        int ixa = (int)xsa, iya = (int)ysa;
        int ixb = (int)xsb, iyb = (int)ysb;
        float lxa = xsa - (float)ixa, lya = ysa - (float)iya;
        float lxb = xsb - (float)ixb, lyb = ysb - (float)iyb;

        const float4* rpa = reinterpret_cast<const float4*>(
            bp + (size_t)iya * (size_t)strideB + (size_t)(ixa * 64));
        const float4* rpb = reinterpret_cast<const float4*>(
            bp + (size_t)iyb * (size_t)strideB + (size_t)(ixb * 64));
        float4 ra = __ldg(rpa);
        float4 rb = __ldg(rpb);

        // --- process A (overlaps B's load latency) ---
        float va0, va1;
        lane_eval(ra, lxa, lya, Ay, By, Cy, Dy, va0, va1);
        float qa0 = __shfl_xor_sync(0xffffffffu, va0, 2);
        float qa1 = __shfl_xor_sync(0xffffffffu, va1, 2);
        float sa = (lane & 2) ? (va1 + qa1) : (va0 + qa0);
        sa += __shfl_xor_sync(0xffffffffu, sa, 1);
        if (storer) out[na * 32u + ocol] = sa;

        // --- process B ---
        float vb0, vb1;
        lane_eval(rb, lxb, lyb, Ay, By, Cy, Dy, vb0, vb1);
        float qb0 = __shfl_xor_sync(0xffffffffu, vb0, 2);
        float qb1 = __shfl_xor_sync(0xffffffffu, vb1, 2);
        float sb = (lane & 2) ? (vb1 + qb1) : (vb0 + qb0);
        sb += __shfl_xor_sync(0xffffffffu, sb, 1);
        if (storer) out[nb * 32u + ocol] = sb;
    }
}

extern "C" void kernel_launch(void* const* d_in, const int* in_sizes, int n_in,
                              void* d_out, int out_size) {
    const float* x   = (const float*)d_in[0];   // (262144, 2) float32
    const float* tab = (const float*)d_in[1];   // (2^22, 2, 16) float32
    float* out = (float*)d_out;                 // (262144, 32) float32

    // Pass 1: dense cell grids (max W^2 = 265225)
    dim3 g1((265225 + 255) / 256, 16);
    densify_kernel<<<g1, 256>>>(tab);

    // Pass 2: window blocks (max NL^2 = 262144)
    dim3 g2((262144 + 255) / 256, 16);
    blockify_kernel<<<g2, 256>>>();

    // Main: 2 warp-roles per point-stream
    unsigned total_warps = (NPTS / PTS_PER_WARP) * 2;       // 16384 warps
    enc_cubic_kernel<<<total_warps * 32 / 256, 256>>>(x, out);
}

// round 17
// speedup vs baseline: 1.4092x; 1.0312x over previous
#include <cuda_runtime.h>
#include <cuda_fp16.h>

#define NPTS  (1u << 18)
#define TMASK 0x3FFFFFu
#define PI2C  2654435761u
#define FSCALE 16384.0f              // 2^14: lift features into fp16 normal range
#define INV_FSCALE 6.103515625e-05f  // 2^-14, exact power of two
#define PTS_PER_WARP 32

// NL[l] = floor(16 * 1.26^l) per reference fp32 math
__device__ __constant__ float c_NL[16] = {
    16.f, 20.f, 25.f, 32.f, 40.f, 50.f, 64.f, 80.f,
    101.f, 128.f, 161.f, 203.f, 256.f, 322.f, 406.f, 512.f
};
__device__ __constant__ int c_NLi[16] = {
    16, 20, 25, 32, 40, 50, 64, 80, 101, 128, 161, 203, 256, 322, 406, 512
};
// Cell-grid width per level: W = NL + 3
__device__ __constant__ int c_W[16] = {
    19, 23, 28, 35, 43, 53, 67, 83, 104, 131, 164, 206, 259, 325, 409, 515
};
// Prefix sums of W^2 (pass-1 dense cell grid)
__device__ __constant__ int c_base[16] = {
    0, 361, 890, 1674, 2899, 4748, 7557, 12046,
    18935, 29751, 46912, 73808, 116244, 183325, 288950, 456231
};
#define DENSE1_TOTAL 721456
// Prefix sums of NL^2 (pass-2 window-block grid)
__device__ __constant__ int c_bbase[16] = {
    0, 256, 656, 1281, 2305, 3905, 6405, 10501,
    16901, 27102, 43486, 69407, 110616, 176152, 279836, 444672
};
#define NBLK_TOTAL 706816
// Block-row stride in bytes for main kernel: NLi * 64
__device__ __constant__ int c_strideB[16] = {
    1024, 1280, 1600, 2048, 2560, 3200, 4096, 5120,
    6464, 8192, 10304, 12992, 16384, 20608, 25984, 32768
};

// Pass-1 scratch: dense per-level cell grids, fp16 feature pairs (2.9 MB)
__device__ __half2 g_dense1[DENSE1_TOTAL];

// Pass-2 scratch: one 64B-aligned block per possible 4x4 window (45.2 MB).
// c[j*4+i] = features of cell (bx+i, by+j).
struct __align__(64) Blk { __half2 c[16]; };
__device__ Blk g_blocks[NBLK_TOTAL];

// ---------------------------------------------------------------------------
// Pass 1 (stable R13 version): hash once per reachable cell.
// ---------------------------------------------------------------------------
__global__ void __launch_bounds__(256)
densify_kernel(const float* __restrict__ tab) {
    int l = blockIdx.y;
    int W = c_W[l];
    int tot = W * W;
    int idx = blockIdx.x * 256 + threadIdx.x;
    if (idx >= tot) return;
    int cy = idx / W;
    int cx = idx - cy * W;
    unsigned h = (((unsigned)cx) ^ ((unsigned)cy * PI2C)) & TMASK;
    const float* r = tab + h * 32u;
    g_dense1[c_base[l] + idx] =
        __floats2half2_rn(__ldg(r + l) * FSCALE, __ldg(r + l + 16) * FSCALE);
}

// ---------------------------------------------------------------------------
// Pass 2 (stable R13 version): one window per thread.
// ---------------------------------------------------------------------------
__global__ void __launch_bounds__(256)
blockify_kernel() {
    int l = blockIdx.y;
    int NLi = c_NLi[l];
    int nblk = NLi * NLi;
    int idx = blockIdx.x * 256 + threadIdx.x;
    if (idx >= nblk) return;
    int by = idx / NLi;
    int bx = idx - by * NLi;
    int W = c_W[l];
    const __half2* src = g_dense1 + c_base[l] + by * W + bx;
    Blk* dst = g_blocks + c_bbase[l] + idx;
#pragma unroll
    for (int j = 0; j < 4; ++j) {
        float4 row;
        __half2* rc = reinterpret_cast<__half2*>(&row);
#pragma unroll
        for (int i = 0; i < 4; ++i) rc[i] = src[j * W + i];
        reinterpret_cast<float4*>(dst->c)[j] = row;
    }
}

// Catmull-Rom weight polynomial coefficients for tap k: w_k(t)=At^3+Bt^2+Ct+D
__device__ __forceinline__ void cub_coef(int k, float& A, float& B, float& C, float& D) {
    if (k == 0)      { A = -0.5f; B =  1.0f; C = -0.5f; D = 0.f; }
    else if (k == 1) { A =  1.5f; B = -2.5f; C =  0.0f; D = 1.f; }
    else if (k == 2) { A = -1.5f; B =  2.0f; C =  0.5f; D = 0.f; }
    else             { A =  0.5f; B = -0.5f; C =  0.0f; D = 0.f; }
}

// fp16 packed row dot: 4 cells (each half2 = both features) x broadcast
// half2 weights. Result half2 = (dot_feat0, dot_feat1).
__device__ __forceinline__ __half2 rowdot_h2(float4 r, __half2 w0, __half2 w1,
                                             __half2 w2, __half2 w3) {
    const __half2* c = reinterpret_cast<const __half2*>(&r);
    __half2 d = __hmul2(c[0], w0);
    d = __hfma2(c[1], w1, d);
    d = __hfma2(c[2], w2, d);
    d = __hfma2(c[3], w3, d);
    return d;
}

// ---------------------------------------------------------------------------
// Main kernel: one warp per point-stream; lane -> (level = lane>>1,
// rowpair = lane&1). Each lane loads rows j and j+2 of its level's window
// block (same 64B line, 2 independent LDG.128), does packed fp16 x-dots,
// fp32 y-combine, one xor-1 shuffle pair; even lanes store float2 -> one
// contiguous 128B store per warp.
// ---------------------------------------------------------------------------
__global__ void __launch_bounds__(256)
enc_cubic_kernel(const float* __restrict__ x,
                 float* __restrict__ out) {
    unsigned gw = (blockIdx.x * 256u + threadIdx.x) >> 5;   // global warp id
    int lane = threadIdx.x & 31;
    int l = lane >> 1;                    // this lane's level
    int ja = lane & 1;                    // first row: 0 or 1
    // second row = ja + 2

    // Lane-constant state
    float NL = c_NL[l];
    int strideB = c_strideB[l];
    const char* bp = reinterpret_cast<const char*>(g_blocks)
                   + (size_t)c_bbase[l] * 64u + (size_t)(ja * 16);
    float Aa, Ba, Ca, Da, Ab, Bb, Cb, Db;
    cub_coef(ja, Aa, Ba, Ca, Da);
    cub_coef(ja + 2, Ab, Bb, Cb, Db);
    // Fold the exact 2^-14 descale into the y-coefficients (fp32 path)
    Aa *= INV_FSCALE; Ba *= INV_FSCALE; Ca *= INV_FSCALE; Da *= INV_FSCALE;
    Ab *= INV_FSCALE; Bb *= INV_FSCALE; Cb *= INV_FSCALE; Db *= INV_FSCALE;

    unsigned pbase = gw * PTS_PER_WARP;
    const float2* xp = reinterpret_cast<const float2*>(x);
    float2* outp = reinterpret_cast<float2*>(out);
    bool storer = ja == 0;

#pragma unroll 4
    for (int it = 0; it < PTS_PER_WARP; ++it) {
        unsigned n = pbase + it;
        float2 p = __ldg(&xp[n]);         // uniform across warp
        float xs = p.x * NL;
        float ys = p.y * NL;
        int ixi = (int)xs;
        int iyi = (int)ys;
        float lx = xs - (float)ixi;
        float ly = ys - (float)iyi;

        // Two rows of this level's window block (same 64B line)
        const float4* rp = reinterpret_cast<const float4*>(
            bp + (size_t)iyi * (size_t)strideB + (size_t)(ixi * 64));
        float4 ra = __ldg(rp);            // row ja
        float4 rb = __ldg(rp + 2);        // row ja+2

        // x-direction Catmull-Rom weights (fp32, then packed to half2)
        float x2 = lx * lx;
        float wx0 = lx * fmaf(lx, fmaf(lx, -0.5f, 1.0f), -0.5f);
        float wx1 = fmaf(x2, fmaf(lx, 1.5f, -2.5f), 1.0f);
        float wx2 = lx * fmaf(lx, fmaf(lx, -1.5f, 2.0f), 0.5f);
        float wx3 = x2 * fmaf(lx, 0.5f, -0.5f);
        __half2 w0 = __float2half2_rn(wx0);
        __half2 w1 = __float2half2_rn(wx1);
        __half2 w2 = __float2half2_rn(wx2);
        __half2 w3 = __float2half2_rn(wx3);

        // This lane's two y weights (descale folded in)
        float wya = fmaf(fmaf(fmaf(Aa, ly, Ba), ly, Ca), ly, Da);
        float wyb = fmaf(fmaf(fmaf(Ab, ly, Bb), ly, Cb), ly, Db);

        // Packed fp16 x-dots, then fp32 y-combine
        float2 da = __half22float2(rowdot_h2(ra, w0, w1, w2, w3));
        float2 db = __half22float2(rowdot_h2(rb, w0, w1, w2, w3));
        float v0 = fmaf(wya, da.x, wyb * db.x);
        float v1 = fmaf(wya, da.y, wyb * db.y);

        // Pair reduction (rows {ja, ja+2} + rows {1-ja, 3-ja})
        v0 += __shfl_xor_sync(0xffffffffu, v0, 1);
        v1 += __shfl_xor_sync(0xffffffffu, v1, 1);

        if (storer)
            outp[n * 16u + l] = make_float2(v0, v1);
    }
}

extern "C" void kernel_launch(void* const* d_in, const int* in_sizes, int n_in,
                              void* d_out, int out_size) {
    const float* x   = (const float*)d_in[0];   // (262144, 2) float32
    const float* tab = (const float*)d_in[1];   // (2^22, 2, 16) float32
    float* out = (float*)d_out;                 // (262144, 32) float32

    // Pass 1: dense cell grids (max W^2 = 265225)
    dim3 g1((265225 + 255) / 256, 16);
    densify_kernel<<<g1, 256>>>(tab);

    // Pass 2: window blocks (max NL^2 = 262144)
    dim3 g2((262144 + 255) / 256, 16);
    blockify_kernel<<<g2, 256>>>();

    // Main: one warp per 32-point stream, 16 levels per warp
    unsigned total_warps = NPTS / PTS_PER_WARP;             // 8192 warps
    enc_cubic_kernel<<<total_warps * 32 / 256, 256>>>(x, out);
}